// round 1
// baseline (speedup 1.0000x reference)
#include <cuda_runtime.h>
#include <math.h>

#define BB 4
#define NN 2048
#define HH 4
#define DD 128
#define TQ 32
#define MC 32

// ---- device scratch (no allocations allowed) ----
__device__ float g_h[(size_t)BB * HH * NN * DD];    // per-head projections [b,h,n,o]
__device__ float g_att[(size_t)BB * HH * NN * DD];  // alpha @ h             [b,h,n,o]
__device__ float g_s[BB * HH * NN];
__device__ float g_d[BB * HH * NN];
__device__ float g_es[BB * HH * NN];
__device__ float g_es2[BB * HH * NN];
__device__ float g_ed[BB * HH * NN];
__device__ float g_ed2[BB * HH * NN];

// ============================================================
// Kernel 1: h[b,h,n,o] = sum_i x[b,n,i] * W[h,i,o]
// block: 256 thr, 16 rows of n; grid (N/16, B)
// ============================================================
__global__ void k_project(const float* __restrict__ x, const float* __restrict__ W) {
    __shared__ float xs[16][DD];
    int b = blockIdx.y, n0 = blockIdx.x * 16, tid = threadIdx.x;
#pragma unroll
    for (int i = 0; i < 8; i++) {
        int j = tid + i * 256;
        xs[j >> 7][j & 127] = x[((size_t)b * NN + n0 + (j >> 7)) * DD + (j & 127)];
    }
    __syncthreads();
    int col = tid & 127, rs = tid >> 7;
    for (int h = 0; h < HH; h++) {
        const float* Wh = W + h * DD * DD;
        float acc[8] = {0.f, 0.f, 0.f, 0.f, 0.f, 0.f, 0.f, 0.f};
        for (int k = 0; k < DD; k++) {
            float wv = Wh[k * DD + col];
#pragma unroll
            for (int r = 0; r < 8; r++) acc[r] += xs[rs * 8 + r][k] * wv;
        }
#pragma unroll
        for (int r = 0; r < 8; r++)
            g_h[((size_t)(b * HH + h) * NN + n0 + rs * 8 + r) * DD + col] = acc[r];
    }
}

// ============================================================
// Kernel 2: per (b,h,n): s = h.a_src, d = h.a_dst, plus exps.
// warp per row. grid 4096 x 256
// ============================================================
__global__ void k_scores(const float* __restrict__ a) {
    int warp = (blockIdx.x * blockDim.x + threadIdx.x) >> 5;  // = bh*NN + n
    int lane = threadIdx.x & 31;
    int hidx = (warp / NN) % HH;
    float4 hv = ((const float4*)(g_h + (size_t)warp * DD))[lane];
    float4 av = ((const float4*)(a + hidx * 2 * DD))[lane];
    float4 bv = ((const float4*)(a + hidx * 2 * DD + DD))[lane];
    float s = hv.x * av.x + hv.y * av.y + hv.z * av.z + hv.w * av.w;
    float d = hv.x * bv.x + hv.y * bv.y + hv.z * bv.z + hv.w * bv.w;
#pragma unroll
    for (int off = 16; off; off >>= 1) {
        s += __shfl_down_sync(0xffffffffu, s, off);
        d += __shfl_down_sync(0xffffffffu, d, off);
    }
    if (!lane) {
        g_s[warp] = s;
        g_es[warp] = expf(s);
        g_es2[warp] = expf(0.2f * s);
        g_d[warp] = d;
        g_ed[warp] = expf(d);
        g_ed2[warp] = expf(0.2f * d);
    }
}

// ============================================================
// Kernel 3: fused masked-softmax + alpha write + (alpha @ h)
// block = one (b,h), 32 query rows. 256 threads.
//   pass1: Z_n (exp factorization, no per-element MUFU)
//   pass2: per 32-wide m chunk: recompute w, normalize, optionally
//          store alpha, accumulate out += w * h[m,:]
// grid (N/TQ, H, B)
// ============================================================
__global__ void k_attn(const int* __restrict__ adj, float* __restrict__ alpha, int write_alpha) {
    __shared__ float d_s[NN], ed_s[NN], ed2_s[NN];   // 24 KB
    __shared__ float h_s[MC][DD];                    // 16 KB
    __shared__ float w_s[TQ][MC + 1];                // 4.2 KB
    __shared__ float srow[TQ], esrow[TQ], es2row[TQ], zrow[TQ], izrow[TQ];

    int b = blockIdx.z, hh = blockIdx.y, q0 = blockIdx.x * TQ;
    int bh = b * HH + hh;
    int tid = threadIdx.x;

    for (int m = tid; m < NN; m += 256) {
        int idx = bh * NN + m;
        d_s[m] = g_d[idx];
        ed_s[m] = g_ed[idx];
        ed2_s[m] = g_ed2[idx];
    }
    if (tid < TQ) {
        int idx = bh * NN + q0 + tid;
        srow[tid] = g_s[idx];
        esrow[tid] = g_es[idx];
        es2row[tid] = g_es2[idx];
    }
    __syncthreads();

    // ---- pass 1: Z per row (warp handles 4 rows) ----
    int wid = tid >> 5, lane = tid & 31;
#pragma unroll
    for (int rr = 0; rr < 4; rr++) {
        int r = wid * 4 + rr;
        const int* arow = adj + ((size_t)(b * NN + q0 + r)) * NN;
        float sr = srow[r], es = esrow[r], es2 = es2row[r];
        float part = 0.f;
        for (int m = lane; m < NN; m += 32) {
            if (arow[m]) {
                float t = sr + d_s[m];
                part += (t >= 0.f) ? es * ed_s[m] : es2 * ed2_s[m];
            }
        }
#pragma unroll
        for (int off = 16; off; off >>= 1) part += __shfl_down_sync(0xffffffffu, part, off);
        if (!lane) zrow[r] = part;
    }
    __syncthreads();
    if (tid < TQ) izrow[tid] = 1.0f / zrow[tid];
    __syncthreads();

    // ---- pass 2: chunked w + GEMM ----
    float acc[2][8];
#pragma unroll
    for (int i = 0; i < 2; i++)
#pragma unroll
        for (int j = 0; j < 8; j++) acc[i][j] = 0.f;

    int rp = tid >> 4, cs = tid & 15;      // GEMM mapping: rows rp*2,rp*2+1; cols cs*8..cs*8+7
    int wrow = tid >> 3, wj0 = (tid & 7) * 4;  // w-tile mapping: 4 m per thread
    const float4* hbase4 = (const float4*)(g_h + (size_t)bh * NN * DD);

    for (int c = 0; c < NN / MC; c++) {
        // stage h[m0:m0+32, :] (coalesced float4 copy)
        const float4* src = hbase4 + (size_t)c * (MC * DD / 4);
#pragma unroll
        for (int i = 0; i < MC * DD / 4 / 256; i++)
            ((float4*)h_s)[tid + i * 256] = src[tid + i * 256];

        // compute normalized w tile (and optionally write alpha)
        {
            int mbase = c * MC + wj0;
            int4 av4 = *(const int4*)(adj + ((size_t)(b * NN + q0 + wrow)) * NN + mbase);
            int avs[4] = {av4.x, av4.y, av4.z, av4.w};
            float sr = srow[wrow], es = esrow[wrow], es2 = es2row[wrow], iz = izrow[wrow];
            float wv[4];
#pragma unroll
            for (int j = 0; j < 4; j++) {
                int m = mbase + j;
                float t = sr + d_s[m];
                float w = (t >= 0.f) ? es * ed_s[m] : es2 * ed2_s[m];
                w = avs[j] ? w * iz : 0.f;
                w_s[wrow][wj0 + j] = w;
                wv[j] = w;
            }
            if (write_alpha) {
                *(float4*)(alpha + ((size_t)(bh * NN + q0 + wrow)) * NN + mbase) =
                    make_float4(wv[0], wv[1], wv[2], wv[3]);
            }
        }
        __syncthreads();

        // 32x128x32 fp32 GEMM tile
        int r0 = rp * 2;
#pragma unroll
        for (int k = 0; k < MC; k++) {
            float w0 = w_s[r0][k], w1 = w_s[r0 + 1][k];
            float4 a0 = *(const float4*)&h_s[k][cs * 8];
            float4 a1 = *(const float4*)&h_s[k][cs * 8 + 4];
            acc[0][0] += w0 * a0.x; acc[0][1] += w0 * a0.y;
            acc[0][2] += w0 * a0.z; acc[0][3] += w0 * a0.w;
            acc[0][4] += w0 * a1.x; acc[0][5] += w0 * a1.y;
            acc[0][6] += w0 * a1.z; acc[0][7] += w0 * a1.w;
            acc[1][0] += w1 * a0.x; acc[1][1] += w1 * a0.y;
            acc[1][2] += w1 * a0.z; acc[1][3] += w1 * a0.w;
            acc[1][4] += w1 * a1.x; acc[1][5] += w1 * a1.y;
            acc[1][6] += w1 * a1.z; acc[1][7] += w1 * a1.w;
        }
        __syncthreads();
    }

    int r0 = rp * 2;
    float* o0 = g_att + ((size_t)(bh * NN + q0 + r0)) * DD + cs * 8;
    *(float4*)o0 = make_float4(acc[0][0], acc[0][1], acc[0][2], acc[0][3]);
    *(float4*)(o0 + 4) = make_float4(acc[0][4], acc[0][5], acc[0][6], acc[0][7]);
    float* o1 = o0 + DD;
    *(float4*)o1 = make_float4(acc[1][0], acc[1][1], acc[1][2], acc[1][3]);
    *(float4*)(o1 + 4) = make_float4(acc[1][4], acc[1][5], acc[1][6], acc[1][7]);
}

// ============================================================
// Kernel 4: concat heads + out_proj + bias
// ============================================================
__global__ void k_outproj(const float* __restrict__ Wp, const float* __restrict__ bias,
                          float* __restrict__ out) {
    __shared__ float cs_t[16][HH * DD];  // 32 KB
    int b = blockIdx.y, n0 = blockIdx.x * 16, tid = threadIdx.x;
#pragma unroll
    for (int i = 0; i < 32; i++) {
        int j = tid + i * 256;
        int r = j >> 9, k = j & 511;
        int head = k >> 7, o = k & 127;
        cs_t[r][k] = g_att[((size_t)(b * HH + head) * NN + n0 + r) * DD + o];
    }
    __syncthreads();
    int col = tid & 127, rs = tid >> 7;
    float bv = bias[col];
    float acc[8] = {bv, bv, bv, bv, bv, bv, bv, bv};
    for (int k = 0; k < HH * DD; k++) {
        float wv = Wp[k * DD + col];
#pragma unroll
        for (int r = 0; r < 8; r++) acc[r] += cs_t[rs * 8 + r][k] * wv;
    }
#pragma unroll
    for (int r = 0; r < 8; r++)
        out[((size_t)b * NN + n0 + rs * 8 + r) * DD + col] = acc[r];
}

// ============================================================
extern "C" void kernel_launch(void* const* d_in, const int* in_sizes, int n_in,
                              void* d_out, int out_size) {
    const float* x    = (const float*)d_in[0];
    const int*   adj  = (const int*)d_in[1];
    const float* W    = (const float*)d_in[2];
    const float* a    = (const float*)d_in[3];
    const float* Wp   = (const float*)d_in[4];
    const float* bias = (const float*)d_in[5];

    const size_t OUT_E = (size_t)BB * NN * DD;            // 1,048,576
    const size_t AL_E  = (size_t)BB * HH * NN * NN;       // 67,108,864

    float* outp = nullptr;
    float* alphap = nullptr;
    int write_alpha = 0;
    int write_out = 0;

    if ((size_t)out_size >= OUT_E + AL_E) {               // tuple: (output, alpha)
        outp = (float*)d_out;
        alphap = (float*)d_out + OUT_E;
        write_alpha = 1;
        write_out = 1;
    } else if ((size_t)out_size >= AL_E) {                // alpha only
        alphap = (float*)d_out;
        write_alpha = 1;
    } else {                                              // output only
        outp = (float*)d_out;
        write_out = 1;
    }

    k_project<<<dim3(NN / 16, BB), 256>>>(x, W);
    k_scores<<<(BB * HH * NN * 32) / 256, 256>>>(a);
    k_attn<<<dim3(NN / TQ, HH, BB), 256>>>(adj, alphap, write_alpha);
    if (write_out)
        k_outproj<<<dim3(NN / 16, BB), 256>>>(Wp, bias, outp);
}

// round 2
// speedup vs baseline: 1.4075x; 1.4075x over previous
#include <cuda_runtime.h>
#include <math.h>

#define BB 4
#define NN 2048
#define HH 4
#define DD 128
#define TQ 64
#define MC 32

// ---- device scratch (no allocations allowed) ----
__device__ float g_h[(size_t)BB * HH * NN * DD];    // per-head projections [b,h,n,o]
__device__ float g_att[(size_t)BB * HH * NN * DD];  // alpha @ h             [b,h,n,o]
__device__ float g_es[BB * HH * NN];    // exp(s)
__device__ float g_es2[BB * HH * NN];   // exp(0.2 s)
__device__ float g_ed[BB * HH * NN];    // exp(d)
__device__ float g_ed2[BB * HH * NN];   // exp(0.2 d)

// packed fp32x2 helpers (ptxas never emits FFMA2 from C++)
#define FMA2(d, a, b, c) \
    asm("fma.rn.f32x2 %0, %1, %2, %3;" : "=l"(d) : "l"(a), "l"(b), "l"(c))
#define PACK2(d, x) \
    asm("mov.b64 %0, {%1, %1};" : "=l"(d) : "r"(__float_as_uint(x)))

__device__ __forceinline__ float lo2(unsigned long long v) {
    return __uint_as_float((unsigned)(v & 0xffffffffull));
}
__device__ __forceinline__ float hi2(unsigned long long v) {
    return __uint_as_float((unsigned)(v >> 32));
}

// ============================================================
// Kernel 1: h[b,h,n,o] = sum_i x[b,n,i] * W[h,i,o]
// block: 256 thr, 16 rows; transposed x in smem + FFMA2.
// grid (N/16, B)
// ============================================================
__global__ void k_project(const float* __restrict__ x, const float* __restrict__ W) {
    __shared__ __align__(16) float xs_t[DD][20];  // [k][row], pad 20 keeps 16B align
    int b = blockIdx.y, n0 = blockIdx.x * 16, tid = threadIdx.x;
#pragma unroll
    for (int i = 0; i < 8; i++) {
        int j = tid + i * 256;
        int r = j >> 7, k = j & 127;
        xs_t[k][r] = x[((size_t)b * NN + n0 + r) * DD + k];
    }
    __syncthreads();
    int col = tid & 127, rs = tid >> 7;  // rs in {0,1}: rows rs*8 .. rs*8+7
    for (int h = 0; h < HH; h++) {
        const float* Wh = W + h * DD * DD + col;
        unsigned long long acc[4] = {0ull, 0ull, 0ull, 0ull};
#pragma unroll 8
        for (int k = 0; k < DD; k++) {
            unsigned long long wp;
            PACK2(wp, Wh[k * DD]);
            ulonglong2 x01 = *(const ulonglong2*)&xs_t[k][rs * 8];
            ulonglong2 x23 = *(const ulonglong2*)&xs_t[k][rs * 8 + 4];
            FMA2(acc[0], wp, x01.x, acc[0]);
            FMA2(acc[1], wp, x01.y, acc[1]);
            FMA2(acc[2], wp, x23.x, acc[2]);
            FMA2(acc[3], wp, x23.y, acc[3]);
        }
        size_t base = ((size_t)(b * HH + h) * NN + n0 + rs * 8) * DD + col;
#pragma unroll
        for (int p = 0; p < 4; p++) {
            g_h[base + (size_t)(2 * p) * DD] = lo2(acc[p]);
            g_h[base + (size_t)(2 * p + 1) * DD] = hi2(acc[p]);
        }
    }
}

// ============================================================
// Kernel 2: per (b,h,n): s = h.a_src, d = h.a_dst -> 4 exps.
// warp per row.
// ============================================================
__global__ void k_scores(const float* __restrict__ a) {
    int warp = (blockIdx.x * blockDim.x + threadIdx.x) >> 5;  // = bh*NN + n
    int lane = threadIdx.x & 31;
    int hidx = (warp / NN) % HH;
    float4 hv = ((const float4*)(g_h + (size_t)warp * DD))[lane];
    float4 av = ((const float4*)(a + hidx * 2 * DD))[lane];
    float4 bv = ((const float4*)(a + hidx * 2 * DD + DD))[lane];
    float s = hv.x * av.x + hv.y * av.y + hv.z * av.z + hv.w * av.w;
    float d = hv.x * bv.x + hv.y * bv.y + hv.z * bv.z + hv.w * bv.w;
#pragma unroll
    for (int off = 16; off; off >>= 1) {
        s += __shfl_down_sync(0xffffffffu, s, off);
        d += __shfl_down_sync(0xffffffffu, d, off);
    }
    if (!lane) {
        g_es[warp] = expf(s);
        g_es2[warp] = expf(0.2f * s);
        g_ed[warp] = expf(d);
        g_ed2[warp] = expf(0.2f * d);
    }
}

// ============================================================
// Kernel 3: fused masked-softmax + alpha write + (alpha @ h)
// block = one (b,h) x 64 query rows, 256 threads, FFMA2 GEMM.
// exp(leaky_relu(s+d)) == max(e^s e^d, e^.2s e^.2d)  (monotone)
// ============================================================
__global__ void __launch_bounds__(256, 4)
k_attn(const int* __restrict__ adj, float* __restrict__ alpha, int write_alpha) {
    __shared__ __align__(16) float ed_s[NN], ed2_s[NN];  // 16 KB
    __shared__ __align__(16) float h_s[MC][DD];          // 16 KB
    __shared__ __align__(16) float w_t[MC][TQ + 4];      // [k][row], 8.7 KB
    __shared__ float esrow[TQ], es2row[TQ], izrow[TQ];

    int b = blockIdx.z, hh = blockIdx.y, q0 = blockIdx.x * TQ;
    int bh = b * HH + hh;
    int tid = threadIdx.x;

    for (int m = tid; m < NN; m += 256) {
        int idx = bh * NN + m;
        ed_s[m] = g_ed[idx];
        ed2_s[m] = g_ed2[idx];
    }
    if (tid < TQ) {
        int idx = bh * NN + q0 + tid;
        esrow[tid] = g_es[idx];
        es2row[tid] = g_es2[idx];
    }
    __syncthreads();

    // ---- pass 1: Z per row (warp handles 8 rows, int4 adjacency) ----
    int wid = tid >> 5, lane = tid & 31;
#pragma unroll
    for (int rr = 0; rr < 8; rr++) {
        int r = wid * 8 + rr;
        const int4* arow = (const int4*)(adj + ((size_t)(b * NN + q0 + r)) * NN);
        float es = esrow[r], es2 = es2row[r];
        float part = 0.f;
        for (int m4 = lane; m4 < NN / 4; m4 += 32) {
            int4 av = arow[m4];
            int m = m4 * 4;
            if (av.x) part += fmaxf(es * ed_s[m],     es2 * ed2_s[m]);
            if (av.y) part += fmaxf(es * ed_s[m + 1], es2 * ed2_s[m + 1]);
            if (av.z) part += fmaxf(es * ed_s[m + 2], es2 * ed2_s[m + 2]);
            if (av.w) part += fmaxf(es * ed_s[m + 3], es2 * ed2_s[m + 3]);
        }
#pragma unroll
        for (int off = 16; off; off >>= 1) part += __shfl_down_sync(0xffffffffu, part, off);
        if (!lane) izrow[r] = part;
    }
    __syncthreads();
    if (tid < TQ) izrow[tid] = 1.0f / izrow[tid];
    __syncthreads();

    // ---- pass 2: chunked w + 64x128 FFMA2 GEMM ----
    unsigned long long acc[4][4];
#pragma unroll
    for (int i = 0; i < 4; i++)
#pragma unroll
        for (int j = 0; j < 4; j++) acc[i][j] = 0ull;

    int rp = tid >> 4, cs = tid & 15;          // GEMM: rows rp*4..+3, cols cs*8..+7
    int wrow = tid >> 2, wj0 = (tid & 3) * 8;  // w tile: 8 m per thread, one row
    const float4* hbase4 = (const float4*)(g_h + (size_t)bh * NN * DD);
    float wes = esrow[wrow], wes2 = es2row[wrow], wiz = izrow[wrow];
    const int* awrow = adj + ((size_t)(b * NN + q0 + wrow)) * NN;
    float* arow_out = alpha + ((size_t)(bh * NN + q0 + wrow)) * NN;

    for (int c = 0; c < NN / MC; c++) {
        // stage h[m0:m0+32, :]
        const float4* src = hbase4 + (size_t)c * (MC * DD / 4);
#pragma unroll
        for (int i = 0; i < 4; i++)
            ((float4*)h_s)[tid + i * 256] = src[tid + i * 256];

        // compute normalized w tile (transposed into w_t)
        {
            int mbase = c * MC + wj0;
            int4 a0 = *(const int4*)(awrow + mbase);
            int4 a1 = *(const int4*)(awrow + mbase + 4);
            int avs[8] = {a0.x, a0.y, a0.z, a0.w, a1.x, a1.y, a1.z, a1.w};
            float wv[8];
#pragma unroll
            for (int j = 0; j < 8; j++) {
                int m = mbase + j;
                float u = fmaxf(wes * ed_s[m], wes2 * ed2_s[m]);
                wv[j] = avs[j] ? u * wiz : 0.f;
                w_t[wj0 + j][wrow] = wv[j];
            }
            if (write_alpha) {
                *(float4*)(arow_out + mbase) = make_float4(wv[0], wv[1], wv[2], wv[3]);
                *(float4*)(arow_out + mbase + 4) = make_float4(wv[4], wv[5], wv[6], wv[7]);
            }
        }
        __syncthreads();

#pragma unroll 8
        for (int k = 0; k < MC; k++) {
            float4 wv4 = *(const float4*)&w_t[k][rp * 4];
            ulonglong2 hA = *(const ulonglong2*)&h_s[k][cs * 8];
            ulonglong2 hB = *(const ulonglong2*)&h_s[k][cs * 8 + 4];
            unsigned long long wp;
            PACK2(wp, wv4.x);
            FMA2(acc[0][0], wp, hA.x, acc[0][0]);
            FMA2(acc[0][1], wp, hA.y, acc[0][1]);
            FMA2(acc[0][2], wp, hB.x, acc[0][2]);
            FMA2(acc[0][3], wp, hB.y, acc[0][3]);
            PACK2(wp, wv4.y);
            FMA2(acc[1][0], wp, hA.x, acc[1][0]);
            FMA2(acc[1][1], wp, hA.y, acc[1][1]);
            FMA2(acc[1][2], wp, hB.x, acc[1][2]);
            FMA2(acc[1][3], wp, hB.y, acc[1][3]);
            PACK2(wp, wv4.z);
            FMA2(acc[2][0], wp, hA.x, acc[2][0]);
            FMA2(acc[2][1], wp, hA.y, acc[2][1]);
            FMA2(acc[2][2], wp, hB.x, acc[2][2]);
            FMA2(acc[2][3], wp, hB.y, acc[2][3]);
            PACK2(wp, wv4.w);
            FMA2(acc[3][0], wp, hA.x, acc[3][0]);
            FMA2(acc[3][1], wp, hA.y, acc[3][1]);
            FMA2(acc[3][2], wp, hB.x, acc[3][2]);
            FMA2(acc[3][3], wp, hB.y, acc[3][3]);
        }
        __syncthreads();
    }

#pragma unroll
    for (int r = 0; r < 4; r++) {
        float* o = g_att + ((size_t)(bh)*NN + q0 + rp * 4 + r) * DD + cs * 8;
        ulonglong2 v0, v1;
        v0.x = acc[r][0]; v0.y = acc[r][1];
        v1.x = acc[r][2]; v1.y = acc[r][3];
        *(ulonglong2*)o = v0;
        *(ulonglong2*)(o + 4) = v1;
    }
}

// ============================================================
// Kernel 4: concat heads + out_proj + bias (transposed + FFMA2)
// ============================================================
__global__ void k_outproj(const float* __restrict__ Wp, const float* __restrict__ bias,
                          float* __restrict__ out) {
    __shared__ __align__(16) float cs_t[HH * DD][20];  // [k][row], 40 KB
    int b = blockIdx.y, n0 = blockIdx.x * 16, tid = threadIdx.x;
#pragma unroll
    for (int i = 0; i < 32; i++) {
        int j = tid + i * 256;
        int r = j >> 9, k = j & 511;
        int head = k >> 7, o = k & 127;
        cs_t[k][r] = g_att[((size_t)(b * HH + head) * NN + n0 + r) * DD + o];
    }
    __syncthreads();
    int col = tid & 127, rs = tid >> 7;
    float bv = bias[col];
    unsigned long long acc[4];
#pragma unroll
    for (int p = 0; p < 4; p++) PACK2(acc[p], bv);
#pragma unroll 8
    for (int k = 0; k < HH * DD; k++) {
        unsigned long long wp;
        PACK2(wp, Wp[k * DD + col]);
        ulonglong2 x01 = *(const ulonglong2*)&cs_t[k][rs * 8];
        ulonglong2 x23 = *(const ulonglong2*)&cs_t[k][rs * 8 + 4];
        FMA2(acc[0], wp, x01.x, acc[0]);
        FMA2(acc[1], wp, x01.y, acc[1]);
        FMA2(acc[2], wp, x23.x, acc[2]);
        FMA2(acc[3], wp, x23.y, acc[3]);
    }
    size_t base = ((size_t)b * NN + n0 + rs * 8) * DD + col;
#pragma unroll
    for (int p = 0; p < 4; p++) {
        out[base + (size_t)(2 * p) * DD] = lo2(acc[p]);
        out[base + (size_t)(2 * p + 1) * DD] = hi2(acc[p]);
    }
}

// ============================================================
extern "C" void kernel_launch(void* const* d_in, const int* in_sizes, int n_in,
                              void* d_out, int out_size) {
    const float* x    = (const float*)d_in[0];
    const int*   adj  = (const int*)d_in[1];
    const float* W    = (const float*)d_in[2];
    const float* a    = (const float*)d_in[3];
    const float* Wp   = (const float*)d_in[4];
    const float* bias = (const float*)d_in[5];

    const size_t OUT_E = (size_t)BB * NN * DD;       // 1,048,576
    const size_t AL_E  = (size_t)BB * HH * NN * NN;  // 67,108,864

    float* outp = nullptr;
    float* alphap = nullptr;
    int write_alpha = 0;
    int write_out = 0;

    if ((size_t)out_size >= OUT_E + AL_E) {
        outp = (float*)d_out;
        alphap = (float*)d_out + OUT_E;
        write_alpha = 1;
        write_out = 1;
    } else if ((size_t)out_size >= AL_E) {
        alphap = (float*)d_out;
        write_alpha = 1;
    } else {
        outp = (float*)d_out;
        write_out = 1;
    }
    if (!alphap) alphap = g_att;  // harmless dummy target (never dereferenced when !write_alpha)

    k_project<<<dim3(NN / 16, BB), 256>>>(x, W);
    k_scores<<<(BB * HH * NN * 32) / 256, 256>>>(a);
    k_attn<<<dim3(NN / TQ, HH, BB), 256>>>(adj, alphap, write_alpha);
    if (write_out)
        k_outproj<<<dim3(NN / 16, BB), 256>>>(Wp, bias, outp);
}

// round 4
// speedup vs baseline: 2.4935x; 1.7715x over previous
#include <cuda_runtime.h>
#include <math.h>

#define BB 4
#define NN 2048
#define HH 4
#define DD 128
#define QB 128   // queries per CTA in tensor attention
#define KC 32    // m-chunk per staged tile
#define PCK 40   // padded packed-row stride (floats)

// ---- device scratch ----
__device__ float g_h[(size_t)BB * HH * NN * DD];     // [b,h,n,o]
__device__ float g_ht[(size_t)BB * HH * DD * NN];    // [b,h,o,n]
__device__ float g_att[(size_t)BB * HH * NN * DD];   // alpha @ h  [b,h,n,o]
__device__ float g_es[BB * HH * NN];
__device__ float g_es2[BB * HH * NN];
__device__ float g_ed[BB * HH * NN];
__device__ float g_ed2[BB * HH * NN];

// ---- packed fp32x2 helpers ----
#define FMA2(d, a, b, c) \
    asm("fma.rn.f32x2 %0, %1, %2, %3;" : "=l"(d) : "l"(a), "l"(b), "l"(c))
#define PACK2(d, x) \
    asm("mov.b64 %0, {%1, %1};" : "=l"(d) : "r"(__float_as_uint(x)))
__device__ __forceinline__ float lo2(unsigned long long v) {
    return __uint_as_float((unsigned)(v & 0xffffffffull));
}
__device__ __forceinline__ float hi2(unsigned long long v) {
    return __uint_as_float((unsigned)(v >> 32));
}

__device__ __forceinline__ unsigned f2tf32(float x) {
    unsigned r;
    asm("cvt.rna.tf32.f32 %0, %1;" : "=r"(r) : "f"(x));
    return r;
}
// pack slot: pairs (m, m+4) adjacent within each 8-wide k-step group
__device__ __forceinline__ int pslot(int m) {
    return ((m >> 3) << 3) + ((m & 3) << 1) + ((m & 7) >> 2);
}

__device__ __forceinline__ void mma_tf32(float* c, unsigned a0, unsigned a1,
                                         unsigned a2, unsigned a3,
                                         unsigned b0, unsigned b1) {
    asm volatile(
        "mma.sync.aligned.m16n8k8.row.col.f32.tf32.tf32.f32 "
        "{%0,%1,%2,%3}, {%4,%5,%6,%7}, {%8,%9}, {%0,%1,%2,%3};"
        : "+f"(c[0]), "+f"(c[1]), "+f"(c[2]), "+f"(c[3])
        : "r"(a0), "r"(a1), "r"(a2), "r"(a3), "r"(b0), "r"(b1));
}

// ============================================================
// Kernel 1: h = x @ W per head; writes g_h and transposed g_ht
// ============================================================
__global__ void k_project(const float* __restrict__ x, const float* __restrict__ W) {
    __shared__ __align__(16) float xs_t[DD][20];
    __shared__ float ht_s[DD][17];
    int b = blockIdx.y, n0 = blockIdx.x * 16, tid = threadIdx.x;
#pragma unroll
    for (int i = 0; i < 8; i++) {
        int j = tid + i * 256;
        int r = j >> 7, k = j & 127;
        xs_t[k][r] = x[((size_t)b * NN + n0 + r) * DD + k];
    }
    __syncthreads();
    int col = tid & 127, rs = tid >> 7;
    for (int h = 0; h < HH; h++) {
        const float* Wh = W + h * DD * DD + col;
        unsigned long long acc[4] = {0ull, 0ull, 0ull, 0ull};
#pragma unroll 8
        for (int k = 0; k < DD; k++) {
            unsigned long long wp;
            PACK2(wp, Wh[k * DD]);
            ulonglong2 x01 = *(const ulonglong2*)&xs_t[k][rs * 8];
            ulonglong2 x23 = *(const ulonglong2*)&xs_t[k][rs * 8 + 4];
            FMA2(acc[0], wp, x01.x, acc[0]);
            FMA2(acc[1], wp, x01.y, acc[1]);
            FMA2(acc[2], wp, x23.x, acc[2]);
            FMA2(acc[3], wp, x23.y, acc[3]);
        }
        size_t base = ((size_t)(b * HH + h) * NN + n0 + rs * 8) * DD + col;
#pragma unroll
        for (int p = 0; p < 4; p++) {
            float vlo = lo2(acc[p]), vhi = hi2(acc[p]);
            g_h[base + (size_t)(2 * p) * DD] = vlo;
            g_h[base + (size_t)(2 * p + 1) * DD] = vhi;
            ht_s[col][rs * 8 + 2 * p] = vlo;
            ht_s[col][rs * 8 + 2 * p + 1] = vhi;
        }
        __syncthreads();
        {
            int o = tid >> 1, j0 = (tid & 1) * 8;
            float* dst = g_ht + ((size_t)(b * HH + h) * DD + o) * NN + n0 + j0;
#pragma unroll
            for (int j = 0; j < 8; j++) dst[j] = ht_s[o][j0 + j];
        }
        __syncthreads();
    }
}

// ============================================================
// Kernel 2: scores -> 4 exps per (b,h,n)
// ============================================================
__global__ void k_scores(const float* __restrict__ a) {
    int warp = (blockIdx.x * blockDim.x + threadIdx.x) >> 5;
    int lane = threadIdx.x & 31;
    int hidx = (warp / NN) % HH;
    float4 hv = ((const float4*)(g_h + (size_t)warp * DD))[lane];
    float4 av = ((const float4*)(a + hidx * 2 * DD))[lane];
    float4 bv = ((const float4*)(a + hidx * 2 * DD + DD))[lane];
    float s = hv.x * av.x + hv.y * av.y + hv.z * av.z + hv.w * av.w;
    float d = hv.x * bv.x + hv.y * bv.y + hv.z * bv.z + hv.w * bv.w;
#pragma unroll
    for (int off = 16; off; off >>= 1) {
        s += __shfl_down_sync(0xffffffffu, s, off);
        d += __shfl_down_sync(0xffffffffu, d, off);
    }
    if (!lane) {
        g_es[warp] = expf(s);
        g_es2[warp] = expf(0.2f * s);
        g_ed[warp] = expf(d);
        g_ed2[warp] = expf(0.2f * d);
    }
}

// ============================================================
// Kernel 3: warp-MMA (tf32) attention. CTA = (b,h) x 128 queries.
// D[q,o] = sum_m w[q,m] * h[m,o]
// exp(leaky_relu(s+d)) == max(e^s e^d, e^.2s e^.2d)
// ============================================================
__global__ void __launch_bounds__(256, 2)
k_attn_mma(const int* __restrict__ adj, float* __restrict__ alpha, int write_alpha) {
    __shared__ float ed_s[NN], ed2_s[NN];                    // 16 KB
    __shared__ __align__(16) unsigned w_pack[QB][PCK];       // 20 KB (tf32 bits)
    __shared__ __align__(16) unsigned h_pack[DD][PCK];       // 20 KB (tf32 bits)
    __shared__ float esr[QB], es2r[QB], izr[QB];

    int b = blockIdx.z, hh = blockIdx.y, q0 = blockIdx.x * QB;
    int bh = b * HH + hh;
    int tid = threadIdx.x, wid = tid >> 5, lane = tid & 31;

    const float* edp = g_ed + bh * NN;
    const float* ed2p = g_ed2 + bh * NN;
    for (int m = tid; m < NN; m += 256) {
        ed_s[m] = edp[m];
        ed2_s[m] = ed2p[m];
    }
    if (tid < QB) {
        int idx = bh * NN + q0 + tid;
        esr[tid] = g_es[idx];
        es2r[tid] = g_es2[idx];
    }
    __syncthreads();

    // ---- Z pass: each warp handles 16 q rows ----
#pragma unroll
    for (int rr = 0; rr < 16; rr++) {
        int r = wid * 16 + rr;
        const int4* arow = (const int4*)(adj + ((size_t)(b * NN + q0 + r)) * NN);
        float es = esr[r], es2 = es2r[r];
        float z = 0.f;
        for (int m4 = lane; m4 < NN / 4; m4 += 32) {
            int4 av = arow[m4];
            int m = m4 * 4;
            if (av.x) z += fmaxf(es * ed_s[m], es2 * ed2_s[m]);
            if (av.y) z += fmaxf(es * ed_s[m + 1], es2 * ed2_s[m + 1]);
            if (av.z) z += fmaxf(es * ed_s[m + 2], es2 * ed2_s[m + 2]);
            if (av.w) z += fmaxf(es * ed_s[m + 3], es2 * ed2_s[m + 3]);
        }
#pragma unroll
        for (int off = 16; off; off >>= 1) z += __shfl_down_sync(0xffffffffu, z, off);
        if (!lane) izr[r] = z;
    }
    __syncthreads();
    if (tid < QB) izr[tid] = 1.0f / izr[tid];
    __syncthreads();

    // ---- main loop ----
    float acc[16][4];
#pragma unroll
    for (int i = 0; i < 16; i++)
#pragma unroll
        for (int j = 0; j < 4; j++) acc[i][j] = 0.f;

    const float4* htp = (const float4*)(g_ht + (size_t)bh * DD * NN);
    int q = tid >> 1, mh = (tid & 1) * 16;                // w producer mapping
    const int4* aqrow = (const int4*)(adj + ((size_t)(b * NN + q0 + q)) * NN);
    float* alrow = alpha + ((size_t)bh * NN + q0 + q) * NN;
    float esq = esr[q], es2q = es2r[q], izq = izr[q];

    int wq0 = wid * 16;                                   // warp q-tile base
    int frow = lane >> 2, fcol = (lane & 3) * 2;          // fragment mapping

    for (int c = 0; c < NN / KC; c++) {
        // gmem prefetch (before the sync)
        float4 hv[4];
#pragma unroll
        for (int i = 0; i < 4; i++) {
            int idx = tid + i * 256;
            int o = idx >> 3, j = idx & 7;
            hv[i] = htp[(size_t)o * (NN / 4) + c * 8 + j];
        }
        int4 aj[4];
#pragma unroll
        for (int g = 0; g < 4; g++) aj[g] = aqrow[(c * KC + mh) / 4 + g];

        // compute w values (fp32 for alpha, tf32 for MMA)
        int aflat[16];
#pragma unroll
        for (int g = 0; g < 4; g++) {
            aflat[g * 4] = aj[g].x; aflat[g * 4 + 1] = aj[g].y;
            aflat[g * 4 + 2] = aj[g].z; aflat[g * 4 + 3] = aj[g].w;
        }
        float wv[16];
#pragma unroll
        for (int j = 0; j < 16; j++) {
            int m = c * KC + mh + j;
            float u = fmaxf(esq * ed_s[m], es2q * ed2_s[m]);
            wv[j] = aflat[j] ? u * izq : 0.f;
        }
        if (write_alpha) {
#pragma unroll
            for (int g = 0; g < 4; g++)
                *(float4*)(alrow + c * KC + mh + g * 4) =
                    make_float4(wv[g * 4], wv[g * 4 + 1], wv[g * 4 + 2], wv[g * 4 + 3]);
        }

        __syncthreads();  // previous chunk's MMA reads done

        // stage h tile (tf32, packed)
#pragma unroll
        for (int i = 0; i < 4; i++) {
            int idx = tid + i * 256;
            int o = idx >> 3, j = idx & 7;
            int m0 = j * 4;
            h_pack[o][pslot(m0)] = f2tf32(hv[i].x);
            h_pack[o][pslot(m0 + 1)] = f2tf32(hv[i].y);
            h_pack[o][pslot(m0 + 2)] = f2tf32(hv[i].z);
            h_pack[o][pslot(m0 + 3)] = f2tf32(hv[i].w);
        }
        // stage w tile (tf32, packed)
#pragma unroll
        for (int j = 0; j < 16; j++) w_pack[q][pslot(mh + j)] = f2tf32(wv[j]);
        __syncthreads();

        // 128q x 128o x 32m warp-MMA
#pragma unroll
        for (int ks = 0; ks < 4; ks++) {
            uint2 aLo = *(const uint2*)&w_pack[wq0 + frow][ks * 8 + fcol];
            uint2 aHi = *(const uint2*)&w_pack[wq0 + 8 + frow][ks * 8 + fcol];
#pragma unroll
            for (int nt = 0; nt < 16; nt++) {
                uint2 bb = *(const uint2*)&h_pack[nt * 8 + frow][ks * 8 + fcol];
                mma_tf32(acc[nt], aLo.x, aHi.x, aLo.y, aHi.y, bb.x, bb.y);
            }
        }
    }

    // epilogue: acc -> g_att[q, o]
#pragma unroll
    for (int nt = 0; nt < 16; nt++) {
        int qq = q0 + wq0 + frow;
        int oo = nt * 8 + fcol;
        float* p0 = g_att + ((size_t)bh * NN + qq) * DD + oo;
        *(float2*)p0 = make_float2(acc[nt][0], acc[nt][1]);
        *(float2*)(p0 + (size_t)8 * DD) = make_float2(acc[nt][2], acc[nt][3]);
    }
}

// ============================================================
// Kernel 4: concat heads + out_proj + bias
// ============================================================
__global__ void k_outproj(const float* __restrict__ Wp, const float* __restrict__ bias,
                          float* __restrict__ out) {
    __shared__ __align__(16) float cs_t[HH * DD][20];
    int b = blockIdx.y, n0 = blockIdx.x * 16, tid = threadIdx.x;
#pragma unroll
    for (int i = 0; i < 32; i++) {
        int j = tid + i * 256;
        int r = j >> 9, k = j & 511;
        int head = k >> 7, o = k & 127;
        cs_t[k][r] = g_att[((size_t)(b * HH + head) * NN + n0 + r) * DD + o];
    }
    __syncthreads();
    int col = tid & 127, rs = tid >> 7;
    float bv = bias[col];
    unsigned long long acc[4];
#pragma unroll
    for (int p = 0; p < 4; p++) PACK2(acc[p], bv);
#pragma unroll 8
    for (int k = 0; k < HH * DD; k++) {
        unsigned long long wp;
        PACK2(wp, Wp[k * DD + col]);
        ulonglong2 x01 = *(const ulonglong2*)&cs_t[k][rs * 8];
        ulonglong2 x23 = *(const ulonglong2*)&cs_t[k][rs * 8 + 4];
        FMA2(acc[0], wp, x01.x, acc[0]);
        FMA2(acc[1], wp, x01.y, acc[1]);
        FMA2(acc[2], wp, x23.x, acc[2]);
        FMA2(acc[3], wp, x23.y, acc[3]);
    }
    size_t base = ((size_t)b * NN + n0 + rs * 8) * DD + col;
#pragma unroll
    for (int p = 0; p < 4; p++) {
        out[base + (size_t)(2 * p) * DD] = lo2(acc[p]);
        out[base + (size_t)(2 * p + 1) * DD] = hi2(acc[p]);
    }
}

// ============================================================
extern "C" void kernel_launch(void* const* d_in, const int* in_sizes, int n_in,
                              void* d_out, int out_size) {
    const float* x    = (const float*)d_in[0];
    const int*   adj  = (const int*)d_in[1];
    const float* W    = (const float*)d_in[2];
    const float* a    = (const float*)d_in[3];
    const float* Wp   = (const float*)d_in[4];
    const float* bias = (const float*)d_in[5];

    const size_t OUT_E = (size_t)BB * NN * DD;
    const size_t AL_E  = (size_t)BB * HH * NN * NN;

    float* outp = nullptr;
    float* alphap = nullptr;
    int write_alpha = 0, write_out = 0;

    if ((size_t)out_size >= OUT_E + AL_E) {
        outp = (float*)d_out;
        alphap = (float*)d_out + OUT_E;
        write_alpha = 1;
        write_out = 1;
    } else if ((size_t)out_size >= AL_E) {
        alphap = (float*)d_out;
        write_alpha = 1;
    } else {
        outp = (float*)d_out;
        write_out = 1;
    }
    if (!alphap) alphap = g_att;  // dummy, never stored to when !write_alpha

    k_project<<<dim3(NN / 16, BB), 256>>>(x, W);
    k_scores<<<(BB * HH * NN * 32) / 256, 256>>>(a);
    k_attn_mma<<<dim3(NN / QB, HH, BB), 256>>>(adj, alphap, write_alpha);
    if (write_out)
        k_outproj<<<dim3(NN / 16, BB), 256>>>(Wp, bias, outp);
}

// round 5
// speedup vs baseline: 2.6366x; 1.0574x over previous
#include <cuda_runtime.h>
#include <math.h>

#define BB 4
#define NN 2048
#define HH 4
#define DD 128
#define QB 64    // queries per CTA in tensor attention
#define KC 32    // m-chunk per staged tile
#define PCK 40   // padded packed-row stride (words)

// ---- device scratch ----
__device__ float g_h[(size_t)BB * HH * NN * DD];     // [b,h,n,o]
__device__ float g_ht[(size_t)BB * HH * DD * NN];    // [b,h,o,n]
__device__ float g_att[(size_t)BB * HH * NN * DD];   // alpha @ h  [b,h,n,o]
__device__ float g_es[BB * HH * NN];
__device__ float g_es2[BB * HH * NN];
__device__ float g_ed[BB * HH * NN];
__device__ float g_ed2[BB * HH * NN];
__device__ unsigned g_wpt[DD][512];                  // out_proj_w, packed tf32 [col][k]

// ---- packed fp32x2 helpers ----
#define FMA2(d, a, b, c) \
    asm("fma.rn.f32x2 %0, %1, %2, %3;" : "=l"(d) : "l"(a), "l"(b), "l"(c))
#define PACK2(d, x) \
    asm("mov.b64 %0, {%1, %1};" : "=l"(d) : "r"(__float_as_uint(x)))
__device__ __forceinline__ float lo2(unsigned long long v) {
    return __uint_as_float((unsigned)(v & 0xffffffffull));
}
__device__ __forceinline__ float hi2(unsigned long long v) {
    return __uint_as_float((unsigned)(v >> 32));
}

__device__ __forceinline__ unsigned f2tf32(float x) {
    unsigned r;
    asm("cvt.rna.tf32.f32 %0, %1;" : "=r"(r) : "f"(x));
    return r;
}
// pack slot: pairs (m, m+4) adjacent within each 8-wide k-step group
__device__ __forceinline__ int pslot(int m) {
    return ((m >> 3) << 3) + ((m & 3) << 1) + ((m & 7) >> 2);
}
__device__ __forceinline__ int pslot8(int j) {  // within one 8-group
    return ((j & 3) << 1) + (j >> 2);
}

__device__ __forceinline__ void mma_tf32(float* c, unsigned a0, unsigned a1,
                                         unsigned a2, unsigned a3,
                                         unsigned b0, unsigned b1) {
    asm volatile(
        "mma.sync.aligned.m16n8k8.row.col.f32.tf32.tf32.f32 "
        "{%0,%1,%2,%3}, {%4,%5,%6,%7}, {%8,%9}, {%0,%1,%2,%3};"
        : "+f"(c[0]), "+f"(c[1]), "+f"(c[2]), "+f"(c[3])
        : "r"(a0), "r"(a1), "r"(a2), "r"(a3), "r"(b0), "r"(b1));
}

// ============================================================
// Kernel 0: pack out_proj_w -> tf32, [col][k] with 8-group pslot
// ============================================================
__global__ void k_prepw(const float* __restrict__ Wp) {
    int idx = blockIdx.x * 256 + threadIdx.x;  // 65536 total
    int k = idx >> 7, col = idx & 127;
    g_wpt[col][(k & ~7) + pslot8(k & 7)] = f2tf32(Wp[k * DD + col]);
}

// ============================================================
// Kernel 1: h = x @ W per head; writes g_h and transposed g_ht
// ============================================================
__global__ void k_project(const float* __restrict__ x, const float* __restrict__ W) {
    __shared__ __align__(16) float xs_t[DD][20];
    __shared__ float ht_s[DD][17];
    int b = blockIdx.y, n0 = blockIdx.x * 16, tid = threadIdx.x;
#pragma unroll
    for (int i = 0; i < 8; i++) {
        int j = tid + i * 256;
        int r = j >> 7, k = j & 127;
        xs_t[k][r] = x[((size_t)b * NN + n0 + r) * DD + k];
    }
    __syncthreads();
    int col = tid & 127, rs = tid >> 7;
    for (int h = 0; h < HH; h++) {
        const float* Wh = W + h * DD * DD + col;
        unsigned long long acc[4] = {0ull, 0ull, 0ull, 0ull};
#pragma unroll 8
        for (int k = 0; k < DD; k++) {
            unsigned long long wp;
            PACK2(wp, Wh[k * DD]);
            ulonglong2 x01 = *(const ulonglong2*)&xs_t[k][rs * 8];
            ulonglong2 x23 = *(const ulonglong2*)&xs_t[k][rs * 8 + 4];
            FMA2(acc[0], wp, x01.x, acc[0]);
            FMA2(acc[1], wp, x01.y, acc[1]);
            FMA2(acc[2], wp, x23.x, acc[2]);
            FMA2(acc[3], wp, x23.y, acc[3]);
        }
        size_t base = ((size_t)(b * HH + h) * NN + n0 + rs * 8) * DD + col;
#pragma unroll
        for (int p = 0; p < 4; p++) {
            float vlo = lo2(acc[p]), vhi = hi2(acc[p]);
            g_h[base + (size_t)(2 * p) * DD] = vlo;
            g_h[base + (size_t)(2 * p + 1) * DD] = vhi;
            ht_s[col][rs * 8 + 2 * p] = vlo;
            ht_s[col][rs * 8 + 2 * p + 1] = vhi;
        }
        __syncthreads();
        {
            int o = tid >> 1, j0 = (tid & 1) * 8;
            float* dst = g_ht + ((size_t)(b * HH + h) * DD + o) * NN + n0 + j0;
#pragma unroll
            for (int j = 0; j < 8; j++) dst[j] = ht_s[o][j0 + j];
        }
        __syncthreads();
    }
}

// ============================================================
// Kernel 2: scores -> 4 exps per (b,h,n)
// ============================================================
__global__ void k_scores(const float* __restrict__ a) {
    int warp = (blockIdx.x * blockDim.x + threadIdx.x) >> 5;
    int lane = threadIdx.x & 31;
    int hidx = (warp / NN) % HH;
    float4 hv = ((const float4*)(g_h + (size_t)warp * DD))[lane];
    float4 av = ((const float4*)(a + hidx * 2 * DD))[lane];
    float4 bv = ((const float4*)(a + hidx * 2 * DD + DD))[lane];
    float s = hv.x * av.x + hv.y * av.y + hv.z * av.z + hv.w * av.w;
    float d = hv.x * bv.x + hv.y * bv.y + hv.z * bv.z + hv.w * bv.w;
#pragma unroll
    for (int off = 16; off; off >>= 1) {
        s += __shfl_down_sync(0xffffffffu, s, off);
        d += __shfl_down_sync(0xffffffffu, d, off);
    }
    if (!lane) {
        g_es[warp] = expf(s);
        g_es2[warp] = expf(0.2f * s);
        g_ed[warp] = expf(d);
        g_ed2[warp] = expf(0.2f * d);
    }
}

// ============================================================
// Kernel 3: warp-MMA (tf32) attention. CTA = (b,h) x 64 queries.
// D[q,o] = sum_m w[q,m] * h[m,o]
// ============================================================
__global__ void __launch_bounds__(256, 2)
k_attn_mma(const int* __restrict__ adj, float* __restrict__ alpha, int write_alpha) {
    __shared__ float ed_s[NN], ed2_s[NN];                // 16 KB
    __shared__ __align__(16) unsigned w_pack[QB][PCK];   // 10 KB
    __shared__ __align__(16) unsigned h_pack[DD][PCK];   // 20 KB
    __shared__ float esr[QB], es2r[QB], izr[QB];

    int b = blockIdx.z, hh = blockIdx.y, q0 = blockIdx.x * QB;
    int bh = b * HH + hh;
    int tid = threadIdx.x, wid = tid >> 5, lane = tid & 31;

    const float* edp = g_ed + bh * NN;
    const float* ed2p = g_ed2 + bh * NN;
    for (int m = tid; m < NN; m += 256) {
        ed_s[m] = edp[m];
        ed2_s[m] = ed2p[m];
    }
    if (tid < QB) {
        int idx = bh * NN + q0 + tid;
        esr[tid] = g_es[idx];
        es2r[tid] = g_es2[idx];
    }
    __syncthreads();

    // ---- Z pass: each warp handles 8 q rows ----
#pragma unroll
    for (int rr = 0; rr < 8; rr++) {
        int r = wid * 8 + rr;
        const int4* arow = (const int4*)(adj + ((size_t)(b * NN + q0 + r)) * NN);
        float es = esr[r], es2 = es2r[r];
        float z = 0.f;
        for (int m4 = lane; m4 < NN / 4; m4 += 32) {
            int4 av = arow[m4];
            int m = m4 * 4;
            if (av.x) z += fmaxf(es * ed_s[m], es2 * ed2_s[m]);
            if (av.y) z += fmaxf(es * ed_s[m + 1], es2 * ed2_s[m + 1]);
            if (av.z) z += fmaxf(es * ed_s[m + 2], es2 * ed2_s[m + 2]);
            if (av.w) z += fmaxf(es * ed_s[m + 3], es2 * ed2_s[m + 3]);
        }
#pragma unroll
        for (int off = 16; off; off >>= 1) z += __shfl_down_sync(0xffffffffu, z, off);
        if (!lane) izr[r] = z;
    }
    __syncthreads();
    if (tid < QB) izr[tid] = 1.0f / izr[tid];
    __syncthreads();

    // ---- main loop ----
    float acc[8][4];
#pragma unroll
    for (int i = 0; i < 8; i++)
#pragma unroll
        for (int j = 0; j < 4; j++) acc[i][j] = 0.f;

    const float4* htp = (const float4*)(g_ht + (size_t)bh * DD * NN);
    int q = tid >> 2, mh = (tid & 3) * 8;                 // w producer mapping
    const int4* aqrow = (const int4*)(adj + ((size_t)(b * NN + q0 + q)) * NN);
    float* alrow = alpha + ((size_t)bh * NN + q0 + q) * NN;
    float esq = esr[q], es2q = es2r[q], izq = izr[q];

    int wq0 = (wid >> 1) * 16, oh = (wid & 1) * 64;       // warp tile: 16q x 64o
    int frow = lane >> 2, fcol = (lane & 3) * 2;

    for (int c = 0; c < NN / KC; c++) {
        // gmem prefetch
        float4 hv[4];
#pragma unroll
        for (int i = 0; i < 4; i++) {
            int idx = tid + i * 256;
            int o = idx >> 3, j = idx & 7;
            hv[i] = htp[(size_t)o * (NN / 4) + c * 8 + j];
        }
        int4 aj0 = aqrow[(c * KC + mh) / 4];
        int4 aj1 = aqrow[(c * KC + mh) / 4 + 1];

        int aflat[8] = {aj0.x, aj0.y, aj0.z, aj0.w, aj1.x, aj1.y, aj1.z, aj1.w};
        float wv[8];
#pragma unroll
        for (int j = 0; j < 8; j++) {
            int m = c * KC + mh + j;
            float u = fmaxf(esq * ed_s[m], es2q * ed2_s[m]);
            wv[j] = aflat[j] ? u * izq : 0.f;
        }
        if (write_alpha) {
            *(float4*)(alrow + c * KC + mh) = make_float4(wv[0], wv[1], wv[2], wv[3]);
            *(float4*)(alrow + c * KC + mh + 4) = make_float4(wv[4], wv[5], wv[6], wv[7]);
        }

        __syncthreads();  // previous chunk's MMA reads done

        // stage h tile (tf32, packed)
#pragma unroll
        for (int i = 0; i < 4; i++) {
            int idx = tid + i * 256;
            int o = idx >> 3, j = idx & 7;
            int m0 = j * 4;
            h_pack[o][pslot(m0)] = f2tf32(hv[i].x);
            h_pack[o][pslot(m0 + 1)] = f2tf32(hv[i].y);
            h_pack[o][pslot(m0 + 2)] = f2tf32(hv[i].z);
            h_pack[o][pslot(m0 + 3)] = f2tf32(hv[i].w);
        }
        // stage w tile (tf32, packed)
#pragma unroll
        for (int j = 0; j < 8; j++) w_pack[q][pslot(mh + j)] = f2tf32(wv[j]);
        __syncthreads();

        // 64q x 128o x 32m warp-MMA (warp: 16q x 64o)
#pragma unroll
        for (int ks = 0; ks < 4; ks++) {
            uint2 aLo = *(const uint2*)&w_pack[wq0 + frow][ks * 8 + fcol];
            uint2 aHi = *(const uint2*)&w_pack[wq0 + 8 + frow][ks * 8 + fcol];
#pragma unroll
            for (int nt = 0; nt < 8; nt++) {
                uint2 bb = *(const uint2*)&h_pack[oh + nt * 8 + frow][ks * 8 + fcol];
                mma_tf32(acc[nt], aLo.x, aHi.x, aLo.y, aHi.y, bb.x, bb.y);
            }
        }
    }

    // epilogue
#pragma unroll
    for (int nt = 0; nt < 8; nt++) {
        int qq = q0 + wq0 + frow;
        int oo = oh + nt * 8 + fcol;
        float* p0 = g_att + ((size_t)bh * NN + qq) * DD + oo;
        *(float2*)p0 = make_float2(acc[nt][0], acc[nt][1]);
        *(float2*)(p0 + (size_t)8 * DD) = make_float2(acc[nt][2], acc[nt][3]);
    }
}

// ============================================================
// Kernel 4: out = concat(g_att) @ Wp + bias, tf32 warp-MMA
// CTA: 64 rows x 128 cols, K = 512 in 16 chunks of 32
// ============================================================
__global__ void __launch_bounds__(256, 2)
k_outproj_mma(const float* __restrict__ bias, float* __restrict__ out) {
    __shared__ __align__(16) unsigned a_pack[QB][PCK];   // 10 KB
    __shared__ __align__(16) unsigned b_pack[DD][PCK];   // 20 KB
    __shared__ float bias_s[DD];

    int tid = threadIdx.x, wid = tid >> 5, lane = tid & 31;
    int row0 = blockIdx.x * QB;                     // global row = b*NN + n
    if (tid < DD) bias_s[tid] = bias[tid];

    float acc[8][4];
#pragma unroll
    for (int i = 0; i < 8; i++)
#pragma unroll
        for (int j = 0; j < 4; j++) acc[i][j] = 0.f;

    int wq0 = (wid >> 1) * 16, oh = (wid & 1) * 64;
    int frow = lane >> 2, fcol = (lane & 3) * 2;
    int sr = tid >> 2, sg = tid & 3;                // A staging: row sr, 8-group sg

    for (int c = 0; c < 16; c++) {
        int head = c >> 2, o0 = (c & 3) * 32;
        // prefetch A: 8 k-values (one 8-group) of row sr
        int grow = row0 + sr;
        int bb_ = grow >> 11, nn_ = grow & 2047;
        const float4* ap =
            (const float4*)(g_att + ((size_t)(bb_ * HH + head) * NN + nn_) * DD + o0 + sg * 8);
        float4 v0 = ap[0], v1 = ap[1];
        // prefetch B (packed copy-through): 4 float4
        uint4 wv[4];
#pragma unroll
        for (int i = 0; i < 4; i++) {
            int j = tid + i * 256;
            int col = j >> 3, f4 = j & 7;
            wv[i] = *(const uint4*)&g_wpt[col][c * 32 + f4 * 4];
        }

        __syncthreads();

        float av[8] = {v0.x, v0.y, v0.z, v0.w, v1.x, v1.y, v1.z, v1.w};
#pragma unroll
        for (int j = 0; j < 8; j++) a_pack[sr][sg * 8 + pslot8(j)] = f2tf32(av[j]);
#pragma unroll
        for (int i = 0; i < 4; i++) {
            int j = tid + i * 256;
            int col = j >> 3, f4 = j & 7;
            *(uint4*)&b_pack[col][f4 * 4] = wv[i];
        }
        __syncthreads();

#pragma unroll
        for (int ks = 0; ks < 4; ks++) {
            uint2 aLo = *(const uint2*)&a_pack[wq0 + frow][ks * 8 + fcol];
            uint2 aHi = *(const uint2*)&a_pack[wq0 + 8 + frow][ks * 8 + fcol];
#pragma unroll
            for (int nt = 0; nt < 8; nt++) {
                uint2 bb = *(const uint2*)&b_pack[oh + nt * 8 + frow][ks * 8 + fcol];
                mma_tf32(acc[nt], aLo.x, aHi.x, aLo.y, aHi.y, bb.x, bb.y);
            }
        }
    }

#pragma unroll
    for (int nt = 0; nt < 8; nt++) {
        int rr = row0 + wq0 + frow;
        int oo = oh + nt * 8 + fcol;
        float b0 = bias_s[oo], b1 = bias_s[oo + 1];
        float* p0 = out + (size_t)rr * DD + oo;
        *(float2*)p0 = make_float2(acc[nt][0] + b0, acc[nt][1] + b1);
        *(float2*)(p0 + (size_t)8 * DD) = make_float2(acc[nt][2] + b0, acc[nt][3] + b1);
    }
}

// ============================================================
extern "C" void kernel_launch(void* const* d_in, const int* in_sizes, int n_in,
                              void* d_out, int out_size) {
    const float* x    = (const float*)d_in[0];
    const int*   adj  = (const int*)d_in[1];
    const float* W    = (const float*)d_in[2];
    const float* a    = (const float*)d_in[3];
    const float* Wp   = (const float*)d_in[4];
    const float* bias = (const float*)d_in[5];

    const size_t OUT_E = (size_t)BB * NN * DD;
    const size_t AL_E  = (size_t)BB * HH * NN * NN;

    float* outp = nullptr;
    float* alphap = nullptr;
    int write_alpha = 0, write_out = 0;

    if ((size_t)out_size >= OUT_E + AL_E) {
        outp = (float*)d_out;
        alphap = (float*)d_out + OUT_E;
        write_alpha = 1;
        write_out = 1;
    } else if ((size_t)out_size >= AL_E) {
        alphap = (float*)d_out;
        write_alpha = 1;
    } else {
        outp = (float*)d_out;
        write_out = 1;
    }
    if (!alphap) alphap = g_att;  // dummy, never stored to when !write_alpha

    k_project<<<dim3(NN / 16, BB), 256>>>(x, W);
    k_scores<<<(BB * HH * NN * 32) / 256, 256>>>(a);
    if (write_out) k_prepw<<<256, 256>>>(Wp);
    k_attn_mma<<<dim3(NN / QB, HH, BB), 256>>>(adj, alphap, write_alpha);
    if (write_out)
        k_outproj_mma<<<(BB * NN) / QB, 256>>>(bias, outp);
}

// round 6
// speedup vs baseline: 2.7316x; 1.0360x over previous
#include <cuda_runtime.h>
#include <math.h>

#define BB 4
#define NN 2048
#define HH 4
#define DD 128
#define QB 64    // queries per CTA in tensor attention
#define PCK 40   // padded packed-row stride (words) for outproj kernel
#define PCKH 36  // h_pack row stride (words)

// ---- device scratch ----
__device__ float g_h[(size_t)BB * HH * NN * DD];     // [b,h,n,o]
__device__ float g_ht[(size_t)BB * HH * DD * NN];    // [b,h,o,n]
__device__ float g_att[(size_t)BB * HH * NN * DD];   // alpha @ h  [b,h,n,o]
__device__ float g_es[BB * HH * NN];
__device__ float g_es2[BB * HH * NN];
__device__ float g_ed[BB * HH * NN];
__device__ float g_ed2[BB * HH * NN];
__device__ unsigned g_wpt[DD][512];                  // out_proj_w, packed tf32 [col][k]

// ---- packed fp32x2 helpers ----
#define FMA2(d, a, b, c) \
    asm("fma.rn.f32x2 %0, %1, %2, %3;" : "=l"(d) : "l"(a), "l"(b), "l"(c))
#define PACK2(d, x) \
    asm("mov.b64 %0, {%1, %1};" : "=l"(d) : "r"(__float_as_uint(x)))
__device__ __forceinline__ float lo2(unsigned long long v) {
    return __uint_as_float((unsigned)(v & 0xffffffffull));
}
__device__ __forceinline__ float hi2(unsigned long long v) {
    return __uint_as_float((unsigned)(v >> 32));
}

__device__ __forceinline__ unsigned f2tf32(float x) {
    unsigned r;
    asm("cvt.rna.tf32.f32 %0, %1;" : "=r"(r) : "f"(x));
    return r;
}
__device__ __forceinline__ int pslot8(int j) {  // (m, m+4) adjacent within 8-group
    return ((j & 3) << 1) + (j >> 2);
}

__device__ __forceinline__ void mma_tf32(float* c, unsigned a0, unsigned a1,
                                         unsigned a2, unsigned a3,
                                         unsigned b0, unsigned b1) {
    asm volatile(
        "mma.sync.aligned.m16n8k8.row.col.f32.tf32.tf32.f32 "
        "{%0,%1,%2,%3}, {%4,%5,%6,%7}, {%8,%9}, {%0,%1,%2,%3};"
        : "+f"(c[0]), "+f"(c[1]), "+f"(c[2]), "+f"(c[3])
        : "r"(a0), "r"(a1), "r"(a2), "r"(a3), "r"(b0), "r"(b1));
}

// ============================================================
// Kernel 0: pack out_proj_w -> tf32, [col][k] with 8-group pslot
// ============================================================
__global__ void k_prepw(const float* __restrict__ Wp) {
    int idx = blockIdx.x * 256 + threadIdx.x;  // 65536 total
    int k = idx >> 7, col = idx & 127;
    g_wpt[col][(k & ~7) + pslot8(k & 7)] = f2tf32(Wp[k * DD + col]);
}

// ============================================================
// Kernel 1: h = x @ W per head; writes g_h and transposed g_ht
// ============================================================
__global__ void k_project(const float* __restrict__ x, const float* __restrict__ W) {
    __shared__ __align__(16) float xs_t[DD][20];
    __shared__ float ht_s[DD][17];
    int b = blockIdx.y, n0 = blockIdx.x * 16, tid = threadIdx.x;
#pragma unroll
    for (int i = 0; i < 8; i++) {
        int j = tid + i * 256;
        int r = j >> 7, k = j & 127;
        xs_t[k][r] = x[((size_t)b * NN + n0 + r) * DD + k];
    }
    __syncthreads();
    int col = tid & 127, rs = tid >> 7;
    for (int h = 0; h < HH; h++) {
        const float* Wh = W + h * DD * DD + col;
        unsigned long long acc[4] = {0ull, 0ull, 0ull, 0ull};
#pragma unroll 8
        for (int k = 0; k < DD; k++) {
            unsigned long long wp;
            PACK2(wp, Wh[k * DD]);
            ulonglong2 x01 = *(const ulonglong2*)&xs_t[k][rs * 8];
            ulonglong2 x23 = *(const ulonglong2*)&xs_t[k][rs * 8 + 4];
            FMA2(acc[0], wp, x01.x, acc[0]);
            FMA2(acc[1], wp, x01.y, acc[1]);
            FMA2(acc[2], wp, x23.x, acc[2]);
            FMA2(acc[3], wp, x23.y, acc[3]);
        }
        size_t base = ((size_t)(b * HH + h) * NN + n0 + rs * 8) * DD + col;
#pragma unroll
        for (int p = 0; p < 4; p++) {
            float vlo = lo2(acc[p]), vhi = hi2(acc[p]);
            g_h[base + (size_t)(2 * p) * DD] = vlo;
            g_h[base + (size_t)(2 * p + 1) * DD] = vhi;
            ht_s[col][rs * 8 + 2 * p] = vlo;
            ht_s[col][rs * 8 + 2 * p + 1] = vhi;
        }
        __syncthreads();
        {
            int o = tid >> 1, j0 = (tid & 1) * 8;
            float* dst = g_ht + ((size_t)(b * HH + h) * DD + o) * NN + n0 + j0;
#pragma unroll
            for (int j = 0; j < 8; j++) dst[j] = ht_s[o][j0 + j];
        }
        __syncthreads();
    }
}

// ============================================================
// Kernel 2: scores -> 4 exps per (b,h,n)
// ============================================================
__global__ void k_scores(const float* __restrict__ a) {
    int warp = (blockIdx.x * blockDim.x + threadIdx.x) >> 5;
    int lane = threadIdx.x & 31;
    int hidx = (warp / NN) % HH;
    float4 hv = ((const float4*)(g_h + (size_t)warp * DD))[lane];
    float4 av = ((const float4*)(a + hidx * 2 * DD))[lane];
    float4 bv = ((const float4*)(a + hidx * 2 * DD + DD))[lane];
    float s = hv.x * av.x + hv.y * av.y + hv.z * av.z + hv.w * av.w;
    float d = hv.x * bv.x + hv.y * bv.y + hv.z * bv.z + hv.w * bv.w;
#pragma unroll
    for (int off = 16; off; off >>= 1) {
        s += __shfl_down_sync(0xffffffffu, s, off);
        d += __shfl_down_sync(0xffffffffu, d, off);
    }
    if (!lane) {
        g_es[warp] = expf(s);
        g_es2[warp] = expf(0.2f * s);
        g_ed[warp] = expf(d);
        g_ed2[warp] = expf(0.2f * d);
    }
}

// ============================================================
// Kernel 3: warp-MMA (tf32) attention. CTA = (b,h) x 64 queries.
// Adjacency pre-packed to bitmask in smem; A-fragments register-
// resident; h_pack swizzled for conflict-free LDS.64.
// ============================================================
__global__ void __launch_bounds__(256, 3)
k_attn_mma(const int* __restrict__ adj, float* __restrict__ alpha, int write_alpha) {
    __shared__ float ed_s[NN], ed2_s[NN];                   // 16 KB
    __shared__ unsigned adjb[QB][66];                       // 16.9 KB (padded)
    __shared__ __align__(16) unsigned h_pack[DD * PCKH];    // 18 KB
    __shared__ float esr[QB], es2r[QB], izr[QB];

    int b = blockIdx.z, hh = blockIdx.y, q0 = blockIdx.x * QB;
    int bh = b * HH + hh;
    int tid = threadIdx.x, wid = tid >> 5, lane = tid & 31;

    const float* edp = g_ed + bh * NN;
    const float* ed2p = g_ed2 + bh * NN;
    for (int m = tid; m < NN; m += 256) {
        ed_s[m] = edp[m];
        ed2_s[m] = ed2p[m];
    }
    if (tid < QB) {
        int idx = bh * NN + q0 + tid;
        esr[tid] = g_es[idx];
        es2r[tid] = g_es2[idx];
    }
    __syncthreads();

    // ---- sweep A: pack adjacency rows into bitmasks ----
    {
        int r = tid >> 2, seg = tid & 3;  // row r, 512-m segment
        const int4* arow =
            (const int4*)(adj + ((size_t)(b * NN + q0 + r)) * NN) + seg * 128;
#pragma unroll 4
        for (int w16 = 0; w16 < 16; w16++) {
            unsigned word = 0;
#pragma unroll
            for (int u = 0; u < 8; u++) {
                int4 v = arow[w16 * 8 + u];
                word |= (v.x != 0 ? 1u : 0u) << (u * 4);
                word |= (v.y != 0 ? 1u : 0u) << (u * 4 + 1);
                word |= (v.z != 0 ? 1u : 0u) << (u * 4 + 2);
                word |= (v.w != 0 ? 1u : 0u) << (u * 4 + 3);
            }
            adjb[r][seg * 16 + w16] = word;
        }
    }
    __syncthreads();

    // ---- sweep B: Z per row from bits ----
#pragma unroll
    for (int rr = 0; rr < 8; rr++) {
        int r = wid * 8 + rr;
        float es = esr[r], es2 = es2r[r];
        float z = 0.f;
        for (int j = 0; j < NN / 32; j++) {
            unsigned w = adjb[r][j];  // broadcast
            if ((w >> lane) & 1u) {
                int m = j * 32 + lane;
                z += fmaxf(es * ed_s[m], es2 * ed2_s[m]);
            }
        }
#pragma unroll
        for (int off = 16; off; off >>= 1) z += __shfl_down_sync(0xffffffffu, z, off);
        if (!lane) izr[r] = z;
    }
    __syncthreads();
    if (tid < QB) izr[tid] = 1.0f / izr[tid];
    __syncthreads();

    // ---- main loop ----
    float acc[8][4];
#pragma unroll
    for (int i = 0; i < 8; i++)
#pragma unroll
        for (int j = 0; j < 4; j++) acc[i][j] = 0.f;

    // staging mapping: thread owns row o, 16-m half
    int o = tid >> 1, half = tid & 1;
    const float4* hp4 =
        (const float4*)(g_ht + ((size_t)bh * DD + o) * NN) + half * 4;
    unsigned swz = 2u * ((unsigned)(o >> 1) & 1u);

    // alpha producer mapping
    int q = tid >> 2, mh = (tid & 3) * 8;
    float* alrow = alpha + ((size_t)bh * NN + q0 + q) * NN;
    float esq = esr[q], es2q = es2r[q], izq = izr[q];

    // fragment mapping
    int wq0 = (wid >> 1) * 16, oh = (wid & 1) * 64;
    int frow = lane >> 2, tig = lane & 3, fcol = tig * 2;
    float p1a = esr[wq0 + frow] * izr[wq0 + frow];
    float p2a = es2r[wq0 + frow] * izr[wq0 + frow];
    float p1b = esr[wq0 + 8 + frow] * izr[wq0 + 8 + frow];
    float p2b = es2r[wq0 + 8 + frow] * izr[wq0 + 8 + frow];
    unsigned fswz = 2u * ((unsigned)(frow >> 1) & 1u);
    const unsigned hrow0 = (unsigned)(oh + frow) * PCKH;

    for (int c = 0; c < NN / 32; c++) {
        // alpha producer: 8 w values + 2 STG.128
        {
            float4 e0 = *(const float4*)&ed_s[c * 32 + mh];
            float4 e1 = *(const float4*)&ed_s[c * 32 + mh + 4];
            float4 f0 = *(const float4*)&ed2_s[c * 32 + mh];
            float4 f1 = *(const float4*)&ed2_s[c * 32 + mh + 4];
            unsigned pb = adjb[q][c] >> mh;
            float wv[8];
            wv[0] = (pb & 1u) ? fmaxf(esq * e0.x, es2q * f0.x) * izq : 0.f;
            wv[1] = (pb & 2u) ? fmaxf(esq * e0.y, es2q * f0.y) * izq : 0.f;
            wv[2] = (pb & 4u) ? fmaxf(esq * e0.z, es2q * f0.z) * izq : 0.f;
            wv[3] = (pb & 8u) ? fmaxf(esq * e0.w, es2q * f0.w) * izq : 0.f;
            wv[4] = (pb & 16u) ? fmaxf(esq * e1.x, es2q * f1.x) * izq : 0.f;
            wv[5] = (pb & 32u) ? fmaxf(esq * e1.y, es2q * f1.y) * izq : 0.f;
            wv[6] = (pb & 64u) ? fmaxf(esq * e1.z, es2q * f1.z) * izq : 0.f;
            wv[7] = (pb & 128u) ? fmaxf(esq * e1.w, es2q * f1.w) * izq : 0.f;
            if (write_alpha) {
                *(float4*)(alrow + c * 32 + mh) = make_float4(wv[0], wv[1], wv[2], wv[3]);
                *(float4*)(alrow + c * 32 + mh + 4) = make_float4(wv[4], wv[5], wv[6], wv[7]);
            }
        }

        // prefetch h (16 floats of row o)
        float hvf[16];
#pragma unroll
        for (int i = 0; i < 4; i++) {
            float4 v = hp4[c * 8 + i];
            hvf[i * 4] = v.x; hvf[i * 4 + 1] = v.y;
            hvf[i * 4 + 2] = v.z; hvf[i * 4 + 3] = v.w;
        }

        __syncthreads();  // previous chunk's MMA reads done

        // stage h tile: 8 STS.64, swizzled layout
#pragma unroll
        for (int g = 0; g < 2; g++) {
            int ks = half * 2 + g;
#pragma unroll
            for (int t = 0; t < 4; t++) {
                uint2 val;
                val.x = f2tf32(hvf[g * 8 + t]);
                val.y = f2tf32(hvf[g * 8 + t + 4]);
                *(uint2*)&h_pack[o * PCKH + (((unsigned)(t * 8 + ks * 2)) ^ swz)] = val;
            }
        }
        __syncthreads();

        // MMA: A fragments computed in registers; B from h_pack
        unsigned br0 = adjb[wq0 + frow][c];
        unsigned br1 = adjb[wq0 + 8 + frow][c];
#pragma unroll
        for (int ks = 0; ks < 4; ks++) {
            int mm = c * 32 + ks * 8 + tig;
            float em = ed_s[mm], e2m = ed2_s[mm];
            float em4 = ed_s[mm + 4], e2m4 = ed2_s[mm + 4];
            int bitm = ks * 8 + tig;
            float a0 = ((br0 >> bitm) & 1u) ? fmaxf(p1a * em, p2a * e2m) : 0.f;
            float a1 = ((br1 >> bitm) & 1u) ? fmaxf(p1b * em, p2b * e2m) : 0.f;
            float a2 = ((br0 >> (bitm + 4)) & 1u) ? fmaxf(p1a * em4, p2a * e2m4) : 0.f;
            float a3 = ((br1 >> (bitm + 4)) & 1u) ? fmaxf(p1b * em4, p2b * e2m4) : 0.f;
            unsigned ua0 = f2tf32(a0), ua1 = f2tf32(a1);
            unsigned ua2 = f2tf32(a2), ua3 = f2tf32(a3);
            unsigned coff = ((unsigned)(tig * 8 + ks * 2)) ^ fswz;
#pragma unroll
            for (int nt = 0; nt < 8; nt++) {
                uint2 bb = *(const uint2*)&h_pack[hrow0 + nt * 8 * PCKH + coff];
                mma_tf32(acc[nt], ua0, ua1, ua2, ua3, bb.x, bb.y);
            }
        }
    }

    // epilogue
#pragma unroll
    for (int nt = 0; nt < 8; nt++) {
        int qq = q0 + wq0 + frow;
        int oo = oh + nt * 8 + fcol;
        float* p0 = g_att + ((size_t)bh * NN + qq) * DD + oo;
        *(float2*)p0 = make_float2(acc[nt][0], acc[nt][1]);
        *(float2*)(p0 + (size_t)8 * DD) = make_float2(acc[nt][2], acc[nt][3]);
    }
}

// ============================================================
// Kernel 4: out = concat(g_att) @ Wp + bias, tf32 warp-MMA
// ============================================================
__global__ void __launch_bounds__(256, 2)
k_outproj_mma(const float* __restrict__ bias, float* __restrict__ out) {
    __shared__ __align__(16) unsigned a_pack[QB][PCK];   // 10 KB
    __shared__ __align__(16) unsigned b_pack[DD][PCK];   // 20 KB
    __shared__ float bias_s[DD];

    int tid = threadIdx.x, wid = tid >> 5, lane = tid & 31;
    int row0 = blockIdx.x * QB;
    if (tid < DD) bias_s[tid] = bias[tid];

    float acc[8][4];
#pragma unroll
    for (int i = 0; i < 8; i++)
#pragma unroll
        for (int j = 0; j < 4; j++) acc[i][j] = 0.f;

    int wq0 = (wid >> 1) * 16, oh = (wid & 1) * 64;
    int frow = lane >> 2, fcol = (lane & 3) * 2;
    int sr = tid >> 2, sg = tid & 3;

    for (int c = 0; c < 16; c++) {
        int head = c >> 2, o0 = (c & 3) * 32;
        int grow = row0 + sr;
        int bb_ = grow >> 11, nn_ = grow & 2047;
        const float4* ap =
            (const float4*)(g_att + ((size_t)(bb_ * HH + head) * NN + nn_) * DD + o0 + sg * 8);
        float4 v0 = ap[0], v1 = ap[1];
        uint4 wv[4];
#pragma unroll
        for (int i = 0; i < 4; i++) {
            int j = tid + i * 256;
            int col = j >> 3, f4 = j & 7;
            wv[i] = *(const uint4*)&g_wpt[col][c * 32 + f4 * 4];
        }

        __syncthreads();

        float av[8] = {v0.x, v0.y, v0.z, v0.w, v1.x, v1.y, v1.z, v1.w};
#pragma unroll
        for (int j = 0; j < 8; j++) a_pack[sr][sg * 8 + pslot8(j)] = f2tf32(av[j]);
#pragma unroll
        for (int i = 0; i < 4; i++) {
            int j = tid + i * 256;
            int col = j >> 3, f4 = j & 7;
            *(uint4*)&b_pack[col][f4 * 4] = wv[i];
        }
        __syncthreads();

#pragma unroll
        for (int ks = 0; ks < 4; ks++) {
            uint2 aLo = *(const uint2*)&a_pack[wq0 + frow][ks * 8 + fcol];
            uint2 aHi = *(const uint2*)&a_pack[wq0 + 8 + frow][ks * 8 + fcol];
#pragma unroll
            for (int nt = 0; nt < 8; nt++) {
                uint2 bb = *(const uint2*)&b_pack[oh + nt * 8 + frow][ks * 8 + fcol];
                mma_tf32(acc[nt], aLo.x, aHi.x, aLo.y, aHi.y, bb.x, bb.y);
            }
        }
    }

#pragma unroll
    for (int nt = 0; nt < 8; nt++) {
        int rr = row0 + wq0 + frow;
        int oo = oh + nt * 8 + fcol;
        float b0 = bias_s[oo], b1 = bias_s[oo + 1];
        float* p0 = out + (size_t)rr * DD + oo;
        *(float2*)p0 = make_float2(acc[nt][0] + b0, acc[nt][1] + b1);
        *(float2*)(p0 + (size_t)8 * DD) = make_float2(acc[nt][2] + b0, acc[nt][3] + b1);
    }
}

// ============================================================
extern "C" void kernel_launch(void* const* d_in, const int* in_sizes, int n_in,
                              void* d_out, int out_size) {
    const float* x    = (const float*)d_in[0];
    const int*   adj  = (const int*)d_in[1];
    const float* W    = (const float*)d_in[2];
    const float* a    = (const float*)d_in[3];
    const float* Wp   = (const float*)d_in[4];
    const float* bias = (const float*)d_in[5];

    const size_t OUT_E = (size_t)BB * NN * DD;
    const size_t AL_E  = (size_t)BB * HH * NN * NN;

    float* outp = nullptr;
    float* alphap = nullptr;
    int write_alpha = 0, write_out = 0;

    if ((size_t)out_size >= OUT_E + AL_E) {
        outp = (float*)d_out;
        alphap = (float*)d_out + OUT_E;
        write_alpha = 1;
        write_out = 1;
    } else if ((size_t)out_size >= AL_E) {
        alphap = (float*)d_out;
        write_alpha = 1;
    } else {
        outp = (float*)d_out;
        write_out = 1;
    }
    if (!alphap) alphap = g_att;  // dummy, never stored to when !write_alpha

    k_project<<<dim3(NN / 16, BB), 256>>>(x, W);
    k_scores<<<(BB * HH * NN * 32) / 256, 256>>>(a);
    if (write_out) k_prepw<<<256, 256>>>(Wp);
    k_attn_mma<<<dim3(NN / QB, HH, BB), 256>>>(adj, alphap, write_alpha);
    if (write_out)
        k_outproj_mma<<<(BB * NN) / QB, 256>>>(bias, outp);
}